// round 13
// baseline (speedup 1.0000x reference)
#include <cuda_runtime.h>
#include <cuda_bf16.h>
#include <cstdint>

#define ENC_DIM 1024
#define TOK_DIM 4096
#define NB 8
#define NT 3000
#define M_TOTAL 4096
#define FRATE 50.0f
#define LN_EPS 1e-5f

// ---------------- HMMA GEMM tiling ----------------
#define BM 128
#define BN 128
#define BK 64                       // bf16 per chunk (4 k16 MMA steps)
#define PADK 72                     // padded row length (bf16) -> 144B rows (36w = 4 mod 32)
#define A_STAGE (BM * PADK * 2)     // 18432 B
#define B_STAGE (BN * PADK * 2)     // 18432 B
#define HG_SMEM (2 * (A_STAGE + B_STAGE))   // 73728 B/CTA -> 2 CTAs/SM
#define NCH_TOT (3 * (ENC_DIM / BK))        // 48 chunks (3 plane pairs x 16)
#define NTILES ((M_TOTAL / BM) * (TOK_DIM / BN))   // 1024
#define PERSIST_GRID 296                            // 2 CTAs x 148 SMs

// ---------------- scratch ----------------
__device__ __nv_bfloat16 g_a_hi[(size_t)M_TOTAL * ENC_DIM];
__device__ __nv_bfloat16 g_a_lo[(size_t)M_TOTAL * ENC_DIM];
__device__ __nv_bfloat16 g_b_hi[(size_t)TOK_DIM * ENC_DIM];
__device__ __nv_bfloat16 g_b_lo[(size_t)TOK_DIM * ENC_DIM];
__device__ float g_h[(size_t)M_TOTAL * TOK_DIM];

// ---------------- PTX helpers ----------------
__device__ __forceinline__ uint32_t smem_u32(const void* p) {
    uint32_t r;
    asm("{ .reg .u64 t; cvta.to.shared.u64 t, %1; cvt.u32.u64 %0, t; }" : "=r"(r) : "l"(p));
    return r;
}
__device__ __forceinline__ void cp_async16(uint32_t s, const void* g) {
    asm volatile("cp.async.cg.shared.global [%0], [%1], 16;" :: "r"(s), "l"(g) : "memory");
}
__device__ __forceinline__ void mma16816(float* d, const uint32_t* a, const uint32_t* b) {
    asm volatile(
        "mma.sync.aligned.m16n8k16.row.col.f32.bf16.bf16.f32 "
        "{%0,%1,%2,%3}, {%4,%5,%6,%7}, {%8,%9}, {%0,%1,%2,%3};"
        : "+f"(d[0]), "+f"(d[1]), "+f"(d[2]), "+f"(d[3])
        : "r"(a[0]), "r"(a[1]), "r"(a[2]), "r"(a[3]), "r"(b[0]), "r"(b[1]));
}

__device__ __forceinline__ void split_bf16(float x, __nv_bfloat16& hi, __nv_bfloat16& lo) {
    hi = __float2bfloat16(x);
    lo = __float2bfloat16(x - __bfloat162float(hi));
}

// ---------------- kernel 1: ragged mean-pool -> bf16 hi/lo planes ----------------
__global__ void __launch_bounds__(256) pool_kernel(const float* __restrict__ x,
                                                   const float* __restrict__ ts) {
    const int tok = blockIdx.x;
    const int b   = tok >> 9;
    const int t   = threadIdx.x;
    const float2 tt = ((const float2*)ts)[tok];
    int s = (int)floorf(tt.x * FRATE);
    int e = (int)floorf(tt.y * FRATE);
    if (e < s + 1) e = s + 1;
    if (e > NT) e = NT;
    const float4* xb = (const float4*)(x + (size_t)b * NT * ENC_DIM);
    float4 acc = make_float4(0.f, 0.f, 0.f, 0.f);
    for (int f = s; f < e; f++) {
        float4 v = xb[(size_t)f * (ENC_DIM / 4) + t];
        acc.x += v.x; acc.y += v.y; acc.z += v.z; acc.w += v.w;
    }
    const float inv = 1.f / (float)(e - s);
    float m[4] = {acc.x * inv, acc.y * inv, acc.z * inv, acc.w * inv};
    __nv_bfloat16 hi[4], lo[4];
    #pragma unroll
    for (int i = 0; i < 4; i++) split_bf16(m[i], hi[i], lo[i]);
    const size_t base = (size_t)tok * ENC_DIM + t * 4;
    *(uint2*)(g_a_hi + base) = *(uint2*)hi;
    *(uint2*)(g_a_lo + base) = *(uint2*)lo;
}

// ---------------- kernel 2: W -> bf16 hi/lo planes ----------------
__global__ void __launch_bounds__(256) wsplit_kernel(const float* __restrict__ W) {
    size_t i = ((size_t)blockIdx.x * 256 + threadIdx.x) * 4;
    float4 v = *(const float4*)(W + i);
    __nv_bfloat16 hi[4], lo[4];
    split_bf16(v.x, hi[0], lo[0]); split_bf16(v.y, hi[1], lo[1]);
    split_bf16(v.z, hi[2], lo[2]); split_bf16(v.w, hi[3], lo[3]);
    *(uint2*)(g_b_hi + i) = *(uint2*)hi;
    *(uint2*)(g_b_lo + i) = *(uint2*)lo;
}

// ---------------- dummy: seats hgemm at the profiled launch slot (#4) ----------
__global__ void dummy_kernel() {}

// ---------------- kernel 3: persistent mma.sync bf16 split GEMM + bias + relu --
// Tile 128x128, warp tile 64x32, 2 CTAs/SM, BK=64, persistent over 1024 tiles.
__global__ void __launch_bounds__(256, 2) hgemm_kernel(const float* __restrict__ bias) {
    extern __shared__ __align__(16) char dsm[];
    const int tid  = threadIdx.x;
    const int wid  = tid >> 5;
    const int lane = tid & 31;
    const int g    = lane >> 2;          // 0..7
    const int t    = lane & 3;           // 0..3
    const int wm   = wid >> 2;           // 0..1 (m half)
    const int wn   = wid & 3;            // 0..3 (n quarter)

    const uint32_t smem0 = smem_u32(dsm);

    const __nv_bfloat16* Apl[3] = {g_a_hi, g_a_hi, g_a_lo};
    const __nv_bfloat16* Bpl[3] = {g_b_hi, g_b_lo, g_b_hi};

    for (int tile = blockIdx.x; tile < NTILES; tile += gridDim.x) {
        const int m0 = (tile >> 5) * BM;
        const int n0 = (tile & 31) * BN;

        float acc[4][4][4];
        #pragma unroll
        for (int i = 0; i < 4; i++)
            #pragma unroll
            for (int j = 0; j < 4; j++)
                #pragma unroll
                for (int q = 0; q < 4; q++) acc[i][j][q] = 0.f;

        // loader: per operand 128 rows x 128B = 1024 x 16B segs; thread does 4 each
        auto load_chunk = [&](int c, int buf) {
            const int p  = c >> 4;                   // plane pair (16 chunks each)
            const int ko = (c & 15) * BK;
            #pragma unroll
            for (int h = 0; h < 4; h++) {
                const int seg = tid + h * 256;
                const int row = seg >> 3;
                const int off = (seg & 7) * 16;      // byte offset in 128B row payload
                const __nv_bfloat16* Ab = Apl[p] + (size_t)(m0 + row) * ENC_DIM + ko;
                cp_async16(smem0 + buf * A_STAGE + row * (PADK * 2) + off,
                           (const char*)Ab + off);
                const __nv_bfloat16* Bb = Bpl[p] + (size_t)(n0 + row) * ENC_DIM + ko;
                cp_async16(smem0 + 2 * A_STAGE + buf * B_STAGE + row * (PADK * 2) + off,
                           (const char*)Bb + off);
            }
        };

        load_chunk(0, 0);
        asm volatile("cp.async.commit_group;" ::: "memory");

        int buf = 0;
        for (int c = 0; c < NCH_TOT; c++) {
            if (c + 1 < NCH_TOT) load_chunk(c + 1, buf ^ 1);
            asm volatile("cp.async.commit_group;" ::: "memory");
            asm volatile("cp.async.wait_group 1;" ::: "memory");
            __syncthreads();

            const char* sAb = dsm + buf * A_STAGE;
            const char* sBb = dsm + 2 * A_STAGE + buf * B_STAGE;
            #pragma unroll
            for (int ks = 0; ks < 4; ks++) {
                const int kb = ks * 32 + t * 4;
                uint32_t a[4][4], bfr[4][2];
                #pragma unroll
                for (int i = 0; i < 4; i++) {
                    const int r = wm * 64 + i * 16 + g;
                    a[i][0] = *(const uint32_t*)(sAb + r * (PADK * 2) + kb);
                    a[i][1] = *(const uint32_t*)(sAb + (r + 8) * (PADK * 2) + kb);
                    a[i][2] = *(const uint32_t*)(sAb + r * (PADK * 2) + kb + 16);
                    a[i][3] = *(const uint32_t*)(sAb + (r + 8) * (PADK * 2) + kb + 16);
                }
                #pragma unroll
                for (int j = 0; j < 4; j++) {
                    const int r = wn * 32 + j * 8 + g;
                    bfr[j][0] = *(const uint32_t*)(sBb + r * (PADK * 2) + kb);
                    bfr[j][1] = *(const uint32_t*)(sBb + r * (PADK * 2) + kb + 16);
                }
                #pragma unroll
                for (int i = 0; i < 4; i++)
                    #pragma unroll
                    for (int j = 0; j < 4; j++) mma16816(acc[i][j], a[i], bfr[j]);
            }
            __syncthreads();
            buf ^= 1;
        }

        // epilogue: bias + relu -> g_h  (no smem use; safe before next tile's loads)
        #pragma unroll
        for (int j = 0; j < 4; j++) {
            const int cb = n0 + wn * 32 + j * 8 + t * 2;
            const float2 bv = *(const float2*)(bias + cb);
            #pragma unroll
            for (int i = 0; i < 4; i++) {
                const int r0 = m0 + wm * 64 + i * 16 + g;
                float2 o0, o1;
                o0.x = fmaxf(acc[i][j][0] + bv.x, 0.f);
                o0.y = fmaxf(acc[i][j][1] + bv.y, 0.f);
                o1.x = fmaxf(acc[i][j][2] + bv.x, 0.f);
                o1.y = fmaxf(acc[i][j][3] + bv.y, 0.f);
                *(float2*)(g_h + (size_t)r0 * TOK_DIM + cb)       = o0;
                *(float2*)(g_h + (size_t)(r0 + 8) * TOK_DIM + cb) = o1;
            }
        }
    }
}

// ---------------- kernel 4: LayerNorm over 4096 -> out ----------------
__global__ void __launch_bounds__(256) ln_kernel(const float* __restrict__ gamma,
                                                 const float* __restrict__ beta,
                                                 float* __restrict__ out) {
    const int rowid = blockIdx.x;
    const int t = threadIdx.x;
    const float4* h4 = (const float4*)(g_h + (size_t)rowid * TOK_DIM);
    float4 v[4];
    float sum = 0.f;
    #pragma unroll
    for (int i = 0; i < 4; i++) {
        v[i] = h4[i * 256 + t];
        sum += v[i].x + v[i].y + v[i].z + v[i].w;
    }
    __shared__ float red1[8], red2[8];
    #pragma unroll
    for (int o = 16; o > 0; o >>= 1) sum += __shfl_xor_sync(0xffffffffu, sum, o);
    if ((t & 31) == 0) red1[t >> 5] = sum;
    __syncthreads();
    float tot = 0.f;
    #pragma unroll
    for (int i = 0; i < 8; i++) tot += red1[i];
    const float mu = tot * (1.f / TOK_DIM);

    float sq = 0.f;
    #pragma unroll
    for (int i = 0; i < 4; i++) {
        float dx = v[i].x - mu, dy = v[i].y - mu, dz = v[i].z - mu, dw = v[i].w - mu;
        sq += dx * dx + dy * dy + dz * dz + dw * dw;
    }
    #pragma unroll
    for (int o = 16; o > 0; o >>= 1) sq += __shfl_xor_sync(0xffffffffu, sq, o);
    if ((t & 31) == 0) red2[t >> 5] = sq;
    __syncthreads();
    float tot2 = 0.f;
    #pragma unroll
    for (int i = 0; i < 8; i++) tot2 += red2[i];
    const float rstd = 1.f / sqrtf(tot2 * (1.f / TOK_DIM) + LN_EPS);

    const float4* g4 = (const float4*)gamma;
    const float4* b4 = (const float4*)beta;
    float4* o4 = (float4*)(out + (size_t)rowid * TOK_DIM);
    #pragma unroll
    for (int i = 0; i < 4; i++) {
        const int idx = i * 256 + t;
        const float4 gv = g4[idx], bv = b4[idx];
        float4 r;
        r.x = (v[i].x - mu) * rstd * gv.x + bv.x;
        r.y = (v[i].y - mu) * rstd * gv.y + bv.y;
        r.z = (v[i].z - mu) * rstd * gv.z + bv.z;
        r.w = (v[i].w - mu) * rstd * gv.w + bv.w;
        o4[idx] = r;
    }
}

// ---------------- launcher ----------------
extern "C" void kernel_launch(void* const* d_in, const int* in_sizes, int n_in,
                              void* d_out, int out_size) {
    const float* x     = (const float*)d_in[0];
    const float* ts    = (const float*)d_in[1];
    const float* W     = (const float*)d_in[2];
    const float* b     = (const float*)d_in[3];
    const float* gamma = (const float*)d_in[4];
    const float* beta  = (const float*)d_in[5];
    float* out = (float*)d_out;

    cudaFuncSetAttribute(hgemm_kernel, cudaFuncAttributeMaxDynamicSharedMemorySize, HG_SMEM);

    pool_kernel<<<M_TOTAL, 256>>>(x, ts);
    wsplit_kernel<<<(TOK_DIM * ENC_DIM) / 1024, 256>>>(W);
    dummy_kernel<<<1, 32>>>();                    // hgemm -> profiled launch slot #4
    hgemm_kernel<<<PERSIST_GRID, 256, HG_SMEM>>>(b);
    ln_kernel<<<M_TOTAL, 256>>>(gamma, beta, out);
}

// round 14
// speedup vs baseline: 1.1477x; 1.1477x over previous
#include <cuda_runtime.h>
#include <cuda_bf16.h>
#include <cstdint>

#define ENC_DIM 1024
#define TOK_DIM 4096
#define NB 8
#define NT 3000
#define M_TOTAL 4096
#define FRATE 50.0f
#define LN_EPS 1e-5f

// ---------------- HMMA GEMM tiling ----------------
#define BM 128
#define BN 128
#define BK 64                       // bf16 per chunk (4 k16 MMA steps)
#define PADK 72                     // padded row length (bf16) -> 144B rows (36w = 4 mod 32)
#define A_STAGE (BM * PADK * 2)     // 18432 B
#define B_STAGE (BN * PADK * 2)     // 18432 B
#define NSTAGE 3
#define HG_SMEM (NSTAGE * (A_STAGE + B_STAGE))   // 110592 B/CTA; 2 CTAs = 221184 <= 228KB/SM
#define NCH_TOT (3 * (ENC_DIM / BK))             // 48 chunks (3 plane pairs x 16)

// ---------------- scratch ----------------
__device__ __nv_bfloat16 g_a_hi[(size_t)M_TOTAL * ENC_DIM];
__device__ __nv_bfloat16 g_a_lo[(size_t)M_TOTAL * ENC_DIM];
__device__ __nv_bfloat16 g_b_hi[(size_t)TOK_DIM * ENC_DIM];
__device__ __nv_bfloat16 g_b_lo[(size_t)TOK_DIM * ENC_DIM];
__device__ float g_h[(size_t)M_TOTAL * TOK_DIM];

// ---------------- PTX helpers ----------------
__device__ __forceinline__ uint32_t smem_u32(const void* p) {
    uint32_t r;
    asm("{ .reg .u64 t; cvta.to.shared.u64 t, %1; cvt.u32.u64 %0, t; }" : "=r"(r) : "l"(p));
    return r;
}
__device__ __forceinline__ void cp_async16(uint32_t s, const void* g) {
    asm volatile("cp.async.cg.shared.global [%0], [%1], 16;" :: "r"(s), "l"(g) : "memory");
}
__device__ __forceinline__ void mma16816(float* d, const uint32_t* a, const uint32_t* b) {
    asm volatile(
        "mma.sync.aligned.m16n8k16.row.col.f32.bf16.bf16.f32 "
        "{%0,%1,%2,%3}, {%4,%5,%6,%7}, {%8,%9}, {%0,%1,%2,%3};"
        : "+f"(d[0]), "+f"(d[1]), "+f"(d[2]), "+f"(d[3])
        : "r"(a[0]), "r"(a[1]), "r"(a[2]), "r"(a[3]), "r"(b[0]), "r"(b[1]));
}

__device__ __forceinline__ void split_bf16(float x, __nv_bfloat16& hi, __nv_bfloat16& lo) {
    hi = __float2bfloat16(x);
    lo = __float2bfloat16(x - __bfloat162float(hi));
}

// ---------------- kernel 1: ragged mean-pool -> bf16 hi/lo planes ----------------
__global__ void __launch_bounds__(256) pool_kernel(const float* __restrict__ x,
                                                   const float* __restrict__ ts) {
    const int tok = blockIdx.x;
    const int b   = tok >> 9;
    const int t   = threadIdx.x;
    const float2 tt = ((const float2*)ts)[tok];
    int s = (int)floorf(tt.x * FRATE);
    int e = (int)floorf(tt.y * FRATE);
    if (e < s + 1) e = s + 1;
    if (e > NT) e = NT;
    const float4* xb = (const float4*)(x + (size_t)b * NT * ENC_DIM);
    float4 acc = make_float4(0.f, 0.f, 0.f, 0.f);
    for (int f = s; f < e; f++) {
        float4 v = xb[(size_t)f * (ENC_DIM / 4) + t];
        acc.x += v.x; acc.y += v.y; acc.z += v.z; acc.w += v.w;
    }
    const float inv = 1.f / (float)(e - s);
    float m[4] = {acc.x * inv, acc.y * inv, acc.z * inv, acc.w * inv};
    __nv_bfloat16 hi[4], lo[4];
    #pragma unroll
    for (int i = 0; i < 4; i++) split_bf16(m[i], hi[i], lo[i]);
    const size_t base = (size_t)tok * ENC_DIM + t * 4;
    *(uint2*)(g_a_hi + base) = *(uint2*)hi;
    *(uint2*)(g_a_lo + base) = *(uint2*)lo;
}

// ---------------- kernel 2: W -> bf16 hi/lo planes ----------------
__global__ void __launch_bounds__(256) wsplit_kernel(const float* __restrict__ W) {
    size_t i = ((size_t)blockIdx.x * 256 + threadIdx.x) * 4;
    float4 v = *(const float4*)(W + i);
    __nv_bfloat16 hi[4], lo[4];
    split_bf16(v.x, hi[0], lo[0]); split_bf16(v.y, hi[1], lo[1]);
    split_bf16(v.z, hi[2], lo[2]); split_bf16(v.w, hi[3], lo[3]);
    *(uint2*)(g_b_hi + i) = *(uint2*)hi;
    *(uint2*)(g_b_lo + i) = *(uint2*)lo;
}

// ---------------- dummy: seats hgemm at the profiled launch slot (#4) ----------
__global__ void dummy_kernel() {}

// ---------------- kernel 3: mma.sync bf16 split GEMM + bias + relu ----------------
// Tile 128x128, warp tile 64x32, 2 CTAs/SM, BK=64, 3 stages, prefetch 2,
// ONE __syncthreads per chunk.  Non-persistent grid (scheduler overlaps waves).
__global__ void __launch_bounds__(256, 2) hgemm_kernel(const float* __restrict__ bias) {
    extern __shared__ __align__(16) char dsm[];
    const int tid  = threadIdx.x;
    const int wid  = tid >> 5;
    const int lane = tid & 31;
    const int g    = lane >> 2;          // 0..7
    const int t    = lane & 3;           // 0..3
    const int wm   = wid >> 2;           // 0..1 (m half)
    const int wn   = wid & 3;            // 0..3 (n quarter)
    const int m0 = blockIdx.y * BM;
    const int n0 = blockIdx.x * BN;

    const uint32_t smem0 = smem_u32(dsm);

    const __nv_bfloat16* Apl[3] = {g_a_hi, g_a_hi, g_a_lo};
    const __nv_bfloat16* Bpl[3] = {g_b_hi, g_b_lo, g_b_hi};

    float acc[4][4][4];
    #pragma unroll
    for (int i = 0; i < 4; i++)
        #pragma unroll
        for (int j = 0; j < 4; j++)
            #pragma unroll
            for (int q = 0; q < 4; q++) acc[i][j][q] = 0.f;

    // loader: per operand 128 rows x 128B = 1024 x 16B segs; thread does 4 each
    auto load_chunk = [&](int c, int st) {
        const int p  = c >> 4;                   // plane pair (16 chunks each)
        const int ko = (c & 15) * BK;
        #pragma unroll
        for (int h = 0; h < 4; h++) {
            const int seg = tid + h * 256;
            const int row = seg >> 3;
            const int off = (seg & 7) * 16;      // byte offset in 128B row payload
            const __nv_bfloat16* Ab = Apl[p] + (size_t)(m0 + row) * ENC_DIM + ko;
            cp_async16(smem0 + st * A_STAGE + row * (PADK * 2) + off,
                       (const char*)Ab + off);
            const __nv_bfloat16* Bb = Bpl[p] + (size_t)(n0 + row) * ENC_DIM + ko;
            cp_async16(smem0 + NSTAGE * A_STAGE + st * B_STAGE + row * (PADK * 2) + off,
                       (const char*)Bb + off);
        }
    };

    // prologue: 2 chunks in flight
    load_chunk(0, 0);
    asm volatile("cp.async.commit_group;" ::: "memory");
    load_chunk(1, 1);
    asm volatile("cp.async.commit_group;" ::: "memory");

    int st = 0;
    for (int c = 0; c < NCH_TOT; c++) {
        asm volatile("cp.async.wait_group 1;" ::: "memory");  // chunk c landed
        __syncthreads();                                      // compute(c-1) done everywhere

        // prefetch chunk c+2 into the stage released by compute(c-1)
        if (c + 2 < NCH_TOT) {
            int st2 = st + 2; if (st2 >= NSTAGE) st2 -= NSTAGE;
            load_chunk(c + 2, st2);
        }
        asm volatile("cp.async.commit_group;" ::: "memory");

        const char* sAb = dsm + st * A_STAGE;
        const char* sBb = dsm + NSTAGE * A_STAGE + st * B_STAGE;
        #pragma unroll
        for (int ks = 0; ks < 4; ks++) {
            const int kb = ks * 32 + t * 4;
            uint32_t a[4][4], bfr[4][2];
            #pragma unroll
            for (int i = 0; i < 4; i++) {
                const int r = wm * 64 + i * 16 + g;
                a[i][0] = *(const uint32_t*)(sAb + r * (PADK * 2) + kb);
                a[i][1] = *(const uint32_t*)(sAb + (r + 8) * (PADK * 2) + kb);
                a[i][2] = *(const uint32_t*)(sAb + r * (PADK * 2) + kb + 16);
                a[i][3] = *(const uint32_t*)(sAb + (r + 8) * (PADK * 2) + kb + 16);
            }
            #pragma unroll
            for (int j = 0; j < 4; j++) {
                const int r = wn * 32 + j * 8 + g;
                bfr[j][0] = *(const uint32_t*)(sBb + r * (PADK * 2) + kb);
                bfr[j][1] = *(const uint32_t*)(sBb + r * (PADK * 2) + kb + 16);
            }
            #pragma unroll
            for (int i = 0; i < 4; i++)
                #pragma unroll
                for (int j = 0; j < 4; j++) mma16816(acc[i][j], a[i], bfr[j]);
        }

        if (++st == NSTAGE) st = 0;
    }

    // epilogue: bias + relu -> g_h
    #pragma unroll
    for (int j = 0; j < 4; j++) {
        const int cb = n0 + wn * 32 + j * 8 + t * 2;
        const float2 bv = *(const float2*)(bias + cb);
        #pragma unroll
        for (int i = 0; i < 4; i++) {
            const int r0 = m0 + wm * 64 + i * 16 + g;
            float2 o0, o1;
            o0.x = fmaxf(acc[i][j][0] + bv.x, 0.f);
            o0.y = fmaxf(acc[i][j][1] + bv.y, 0.f);
            o1.x = fmaxf(acc[i][j][2] + bv.x, 0.f);
            o1.y = fmaxf(acc[i][j][3] + bv.y, 0.f);
            *(float2*)(g_h + (size_t)r0 * TOK_DIM + cb)       = o0;
            *(float2*)(g_h + (size_t)(r0 + 8) * TOK_DIM + cb) = o1;
        }
    }
}

// ---------------- kernel 4: LayerNorm over 4096 -> out ----------------
__global__ void __launch_bounds__(256) ln_kernel(const float* __restrict__ gamma,
                                                 const float* __restrict__ beta,
                                                 float* __restrict__ out) {
    const int rowid = blockIdx.x;
    const int t = threadIdx.x;
    const float4* h4 = (const float4*)(g_h + (size_t)rowid * TOK_DIM);
    float4 v[4];
    float sum = 0.f;
    #pragma unroll
    for (int i = 0; i < 4; i++) {
        v[i] = h4[i * 256 + t];
        sum += v[i].x + v[i].y + v[i].z + v[i].w;
    }
    __shared__ float red1[8], red2[8];
    #pragma unroll
    for (int o = 16; o > 0; o >>= 1) sum += __shfl_xor_sync(0xffffffffu, sum, o);
    if ((t & 31) == 0) red1[t >> 5] = sum;
    __syncthreads();
    float tot = 0.f;
    #pragma unroll
    for (int i = 0; i < 8; i++) tot += red1[i];
    const float mu = tot * (1.f / TOK_DIM);

    float sq = 0.f;
    #pragma unroll
    for (int i = 0; i < 4; i++) {
        float dx = v[i].x - mu, dy = v[i].y - mu, dz = v[i].z - mu, dw = v[i].w - mu;
        sq += dx * dx + dy * dy + dz * dz + dw * dw;
    }
    #pragma unroll
    for (int o = 16; o > 0; o >>= 1) sq += __shfl_xor_sync(0xffffffffu, sq, o);
    if ((t & 31) == 0) red2[t >> 5] = sq;
    __syncthreads();
    float tot2 = 0.f;
    #pragma unroll
    for (int i = 0; i < 8; i++) tot2 += red2[i];
    const float rstd = 1.f / sqrtf(tot2 * (1.f / TOK_DIM) + LN_EPS);

    const float4* g4 = (const float4*)gamma;
    const float4* b4 = (const float4*)beta;
    float4* o4 = (float4*)(out + (size_t)rowid * TOK_DIM);
    #pragma unroll
    for (int i = 0; i < 4; i++) {
        const int idx = i * 256 + t;
        const float4 gv = g4[idx], bv = b4[idx];
        float4 r;
        r.x = (v[i].x - mu) * rstd * gv.x + bv.x;
        r.y = (v[i].y - mu) * rstd * gv.y + bv.y;
        r.z = (v[i].z - mu) * rstd * gv.z + bv.z;
        r.w = (v[i].w - mu) * rstd * gv.w + bv.w;
        o4[idx] = r;
    }
}

// ---------------- launcher ----------------
extern "C" void kernel_launch(void* const* d_in, const int* in_sizes, int n_in,
                              void* d_out, int out_size) {
    const float* x     = (const float*)d_in[0];
    const float* ts    = (const float*)d_in[1];
    const float* W     = (const float*)d_in[2];
    const float* b     = (const float*)d_in[3];
    const float* gamma = (const float*)d_in[4];
    const float* beta  = (const float*)d_in[5];
    float* out = (float*)d_out;

    cudaFuncSetAttribute(hgemm_kernel, cudaFuncAttributeMaxDynamicSharedMemorySize, HG_SMEM);

    pool_kernel<<<M_TOTAL, 256>>>(x, ts);
    wsplit_kernel<<<(TOK_DIM * ENC_DIM) / 1024, 256>>>(W);
    dummy_kernel<<<1, 32>>>();                    // hgemm stays at profiled launch slot #4
    dim3 gg(TOK_DIM / BN, M_TOTAL / BM);          // 32 x 32
    hgemm_kernel<<<gg, 256, HG_SMEM>>>(b);
    ln_kernel<<<M_TOTAL, 256>>>(gamma, beta, out);
}